// round 12
// baseline (speedup 1.0000x reference)
#include <cuda_runtime.h>
#include <cuda_fp16.h>
#include <math.h>
#include <cstdint>

#define BATCH 4
#define SEQ   2048
#define DM    1024
#define NH    16
#define HD    64
#define QKVN  (3*DM)
#define MROWS (BATCH*SEQ)   // 8192

// ---------------------------------------------------------------------------
// Persistent fp16 arrays (no dynamic allocation allowed)
// ---------------------------------------------------------------------------
__device__ __half g_xh[(size_t)MROWS * DM];
__device__ __half g_wqh[(size_t)DM * QKVN];
__device__ __half g_woh[(size_t)DM * DM];
__device__ __half g_qkvh[(size_t)MROWS * QKVN];
__device__ __half g_atth[(size_t)MROWS * DM];

// ===========================================================================
// Helpers
// ===========================================================================
__device__ __forceinline__ void ldsm_x4(uint32_t* r, uint32_t addr) {
    asm volatile("ldmatrix.sync.aligned.m8n8.x4.shared.b16 {%0,%1,%2,%3}, [%4];"
        : "=r"(r[0]), "=r"(r[1]), "=r"(r[2]), "=r"(r[3]) : "r"(addr));
}
__device__ __forceinline__ void ldsm_x4_t(uint32_t* r, uint32_t addr) {
    asm volatile("ldmatrix.sync.aligned.m8n8.x4.trans.shared.b16 {%0,%1,%2,%3}, [%4];"
        : "=r"(r[0]), "=r"(r[1]), "=r"(r[2]), "=r"(r[3]) : "r"(addr));
}
__device__ __forceinline__ void ldsm_x2_t(uint32_t* r, uint32_t addr) {
    asm volatile("ldmatrix.sync.aligned.m8n8.x2.trans.shared.b16 {%0,%1}, [%2];"
        : "=r"(r[0]), "=r"(r[1]) : "r"(addr));
}
__device__ __forceinline__ void mma16816(float* d, const uint32_t* a, const uint32_t* b) {
    asm volatile(
        "mma.sync.aligned.m16n8k16.row.col.f32.f16.f16.f32 "
        "{%0,%1,%2,%3}, {%4,%5,%6,%7}, {%8,%9}, {%0,%1,%2,%3};"
        : "+f"(d[0]), "+f"(d[1]), "+f"(d[2]), "+f"(d[3])
        : "r"(a[0]), "r"(a[1]), "r"(a[2]), "r"(a[3]), "r"(b[0]), "r"(b[1]));
}
__device__ __forceinline__ uint32_t smem_to_u32(const void* smem_ptr) {
    uint32_t addr;
    asm("{ .reg .u64 tmp; cvta.to.shared.u64 tmp, %1; cvt.u32.u64 %0, tmp; }"
        : "=r"(addr) : "l"(smem_ptr));
    return addr;
}
__device__ __forceinline__ float ex2f(float x) {
    float y;
    asm("ex2.approx.f32 %0, %1;" : "=f"(y) : "f"(x));
    return y;
}
__device__ __forceinline__ uint32_t pack_h2(float x0, float x1) {
    __half2 t = __floats2half2_rn(x0, x1);
    return *(uint32_t*)&t;
}
__device__ __forceinline__ uint32_t h2ex2(uint32_t x) {
    uint32_t y;
    asm("ex2.approx.f16x2 %0, %1;" : "=r"(y) : "r"(x));
    return y;
}

#define CP_ASYNC16(saddr, gptr) \
    asm volatile("cp.async.cg.shared.global [%0], [%1], 16;" \
                 :: "r"(saddr), "l"(gptr))
#define CP_COMMIT()  asm volatile("cp.async.commit_group;")
#define CP_WAIT0()   asm volatile("cp.async.wait_group 0;")
#define CP_WAIT1()   asm volatile("cp.async.wait_group 1;")

// ===========================================================================
// Convert kernel: fp32 -> fp16
// ===========================================================================
__global__ void cvt_kernel(const float* __restrict__ s,
                           __half* __restrict__ h, int n4)
{
    int i = blockIdx.x * blockDim.x + threadIdx.x;
    if (i >= n4) return;
    float4 v = ((const float4*)s)[i];
    ((uint2*)h)[i] = make_uint2(pack_h2(v.x, v.y), pack_h2(v.z, v.w));
}

// ===========================================================================
// cp.async fp16 GEMM: C = A @ B, fp16 operands, fp32 accumulate.
// CTA tile 128x256, BK=64, 512 threads (16 warps, 32x64 warp tiles, 4x4).
// 3-stage cp.async ring.
// ===========================================================================
#define GOA 0
#define GOB 18432                        // A: 128 rows x 144 B
#define GSTAGE_B 52224                   // + B: 64 rows x 528 B
#define GEMM_SMEM_BYTES (3 * GSTAGE_B)   // 156672

__global__ __launch_bounds__(512, 1)
void gemm_async(const __half* __restrict__ A, const __half* __restrict__ B,
                float* __restrict__ Cf, __half* __restrict__ Ch,
                int M, int N, int K, float qscale, int qcols)
{
    extern __shared__ char smem[];
    const uint32_t su = smem_to_u32(smem);

    const int tid = threadIdx.x;
    const int wid = tid >> 5;
    const int lid = tid & 31;
    const int brow = blockIdx.y * 128;
    const int bcol = blockIdx.x * 256;

    const int wr = wid >> 2;     // 0..3 -> m offset wr*32
    const int wc = wid & 3;      // 0..3 -> n offset wc*64

    const int nkt = K >> 6;      // BK = 64

    // copy-thread assignments (512 threads)
    const int ar  = tid >> 2;            // A row 0..127
    const int ac2 = (tid & 3) * 2;       // A chunk base (2 chunks of 16B)
    const int br  = tid >> 3;            // B row 0..63
    const int bc4 = (tid & 7) * 4;       // B chunk base (4 chunks of 16B)

    auto issue_tile = [&](int kt) {
        const uint32_t sb = su + (uint32_t)(kt % 3) * GSTAGE_B;
        const int k0 = kt << 6;
        const __half* ga = A + (size_t)(brow + ar) * K + k0 + ac2 * 8;
        uint32_t sa = sb + GOA + ar * 144 + ac2 * 16;
        CP_ASYNC16(sa,      ga);
        CP_ASYNC16(sa + 16, ga + 8);
        const __half* gb = B + (size_t)(k0 + br) * N + bcol + bc4 * 8;
        uint32_t sbb = sb + GOB + br * 528 + bc4 * 16;
#pragma unroll
        for (int c = 0; c < 4; c++)
            CP_ASYNC16(sbb + c * 16, gb + c * 8);
    };

    float acc[2][8][4];
#pragma unroll
    for (int i = 0; i < 2; i++)
#pragma unroll
        for (int j = 0; j < 8; j++)
#pragma unroll
            for (int q = 0; q < 4; q++) acc[i][j][q] = 0.f;

    issue_tile(0); CP_COMMIT();
    issue_tile(1); CP_COMMIT();

    for (int kt = 0; kt < nkt; kt++) {
        if (kt + 1 < nkt) { CP_WAIT1(); } else { CP_WAIT0(); }
        __syncthreads();
        if (kt + 2 < nkt) { issue_tile(kt + 2); CP_COMMIT(); }

        const uint32_t sb = su + (uint32_t)(kt % 3) * GSTAGE_B;
#pragma unroll
        for (int ks = 0; ks < 4; ks++) {
            uint32_t ah[2][4];
#pragma unroll
            for (int mi = 0; mi < 2; mi++) {
                uint32_t row = wr * 32 + mi * 16 + (lid & 15);
                uint32_t col = ks * 16 + (lid >> 4) * 8;
                ldsm_x4(ah[mi], sb + GOA + row * 144 + col * 2);
            }
#pragma unroll
            for (int nbp = 0; nbp < 2; nbp++) {
                uint32_t bh[2][4];
#pragma unroll
                for (int i = 0; i < 2; i++) {
                    const int nb = nbp * 2 + i;
                    uint32_t row = ks * 16 + (lid & 15);
                    uint32_t col = wc * 64 + nb * 16 + (lid >> 4) * 8;
                    ldsm_x4_t(bh[i], sb + GOB + row * 528 + col * 2);
                }
#pragma unroll
                for (int i = 0; i < 2; i++) {
                    const int nb = nbp * 2 + i;
#pragma unroll
                    for (int mi = 0; mi < 2; mi++) {
                        mma16816(acc[mi][nb * 2],     ah[mi], &bh[i][0]);
                        mma16816(acc[mi][nb * 2 + 1], ah[mi], &bh[i][2]);
                    }
                }
            }
        }
    }

    // ---- epilogue ----
    const int qrow = lid >> 2;
    const int qcol = (lid & 3) * 2;
#pragma unroll
    for (int mi = 0; mi < 2; mi++) {
        int r0 = brow + wr * 32 + mi * 16 + qrow;
#pragma unroll
        for (int nb8 = 0; nb8 < 8; nb8++) {
            int c0 = bcol + wc * 64 + nb8 * 8 + qcol;
            float* d = acc[mi][nb8];
            if (Cf) {
                *(float2*)(Cf + (size_t)r0 * N + c0)       = make_float2(d[0], d[1]);
                *(float2*)(Cf + (size_t)(r0 + 8) * N + c0) = make_float2(d[2], d[3]);
            } else {
                const float sc = (c0 < qcols) ? qscale : 1.f;
                *(uint32_t*)(Ch + (size_t)r0 * N + c0)       = pack_h2(d[0] * sc, d[1] * sc);
                *(uint32_t*)(Ch + (size_t)(r0 + 8) * N + c0) = pack_h2(d[2] * sc, d[3] * sc);
            }
        }
    }
}

// ===========================================================================
// HMMA flash attention, pure fp16 operands, fp32 accumulate.
// Grid: (SEQ/256, NH, BATCH). 512 threads = 16 warps; warp w owns q rows
// [w*16, w*16+16). Q persists in smem; K/V 3-stage cp.async ring.
// Row-sum l via ones-column in V (extra n8 MMA); P exp via ex2.approx.f16x2.
// ===========================================================================
#define SK 72                          // fp16 elems per row (144 B stride)
#define AQ  0
#define AKV (256 * SK * 2)             // 36864
#define KVST (2 * 64 * SK * 2)         // 18432 per stage (K + V)
#define OKH  0
#define OVH  (64 * SK * 2)             // 9216
#define ATTN_SMEM_BYTES (AKV + 3 * KVST)   // 92160

__global__ __launch_bounds__(512, 1)
void attn_hmma()
{
    extern __shared__ char dsm[];
    const uint32_t su = smem_to_u32(dsm);

    const int tid = threadIdx.x;
    const int wid = tid >> 5;
    const int lid = tid & 31;
    const int b  = blockIdx.z;
    const int h  = blockIdx.y;
    const int q0 = blockIdx.x * 256;

    const uint32_t uQ = su + AQ;

    // KV copy (512 thr): arr = tid>>8 (0:K 1:V), row = (tid>>2)&63, quarter = tid&3
    const int cv_arr = tid >> 8;
    const int cv_r   = (tid >> 2) & 63;
    const int cv_q   = tid & 3;
    const int cv_col = DM + cv_arr * DM + h * HD + cv_q * 16;

    auto issue_kv = [&](int kb) {
        const uint32_t sb = su + AKV + (uint32_t)(kb % 3) * KVST
                            + cv_arr * (64 * SK * 2) + cv_r * (SK * 2) + cv_q * 32;
        const __half* gp = g_qkvh + (size_t)(b * SEQ + kb * 64 + cv_r) * QKVN + cv_col;
        CP_ASYNC16(sb,      gp);
        CP_ASYNC16(sb + 16, gp + 8);
    };

    // ---- init ones-column (cols 64..71) in all 3 V stages; cp.async never
    //      touches these bytes. Visible after the first __syncthreads.
    for (int i = tid; i < 3 * 64; i += 512) {
        int st = i >> 6, r = i & 63;
        char* p = dsm + AKV + st * KVST + OVH + r * (SK * 2) + 128;
        *(uint4*)p = make_uint4(0x00003C00u, 0u, 0u, 0u);   // {1.0h, 0 x7}
    }

    // ---- issue Q + KV block 0 as group 0
    {
        const int qr = tid >> 1;
        const int qc = (tid & 1) * 32;
        const __half* gq = g_qkvh + (size_t)(b * SEQ + q0 + qr) * QKVN + h * HD + qc;
        uint32_t sq = uQ + qr * (SK * 2) + qc * 2;
#pragma unroll
        for (int c = 0; c < 4; c++)
            CP_ASYNC16(sq + c * 16, gq + c * 8);
    }
    issue_kv(0); CP_COMMIT();
    issue_kv(1); CP_COMMIT();

    float o[8][4];
#pragma unroll
    for (int j = 0; j < 8; j++)
#pragma unroll
        for (int q = 0; q < 4; q++) o[j][q] = 0.f;
    float ol[4] = {0.f, 0.f, 0.f, 0.f};     // ones-column accumulator (l)
    float m0 = -1e30f, m1 = -1e30f;

    for (int kb = 0; kb < SEQ / 64; kb++) {
        if (kb + 1 < SEQ / 64) { CP_WAIT1(); } else { CP_WAIT0(); }
        __syncthreads();
        if (kb + 2 < SEQ / 64) { issue_kv(kb + 2); CP_COMMIT(); }

        const uint32_t stB = su + AKV + (uint32_t)(kb % 3) * KVST;
        const uint32_t uKh = stB + OKH, uVh = stB + OVH;

        // ---- S = Q Kh^T  (16 x 64 per warp)
        float s[8][4];
#pragma unroll
        for (int j = 0; j < 8; j++)
#pragma unroll
            for (int q = 0; q < 4; q++) s[j][q] = 0.f;

#pragma unroll
        for (int t = 0; t < 4; t++) {
            uint32_t qh[4];
            {
                uint32_t row = wid * 16 + (lid & 15);
                uint32_t off = (row * SK + t * 16 + (lid >> 4) * 8) * 2;
                ldsm_x4(qh, uQ + off);
            }
#pragma unroll
            for (int jp = 0; jp < 2; jp++) {
                uint32_t kh[2][4];
#pragma unroll
                for (int i = 0; i < 2; i++) {
                    const int j2 = jp * 2 + i;
                    uint32_t off = ((j2 * 16 + (lid & 7) + ((lid >> 4) & 1) * 8) * SK
                                    + t * 16 + ((lid >> 3) & 1) * 8) * 2;
                    ldsm_x4(kh[i], uKh + off);
                }
#pragma unroll
                for (int i = 0; i < 2; i++) {
                    const int j2 = jp * 2 + i;
                    mma16816(s[j2 * 2],     qh, &kh[i][0]);
                    mma16816(s[j2 * 2 + 1], qh, &kh[i][2]);
                }
            }
        }

        // ---- online softmax (log2 domain): max, rescale, P = ex2.f16x2
        uint32_t ph[4][4];
        {
            float mx0 = s[0][0], mx1 = s[0][2];
#pragma unroll
            for (int j = 0; j < 8; j++) {
                mx0 = fmaxf(mx0, fmaxf(s[j][0], s[j][1]));
                mx1 = fmaxf(mx1, fmaxf(s[j][2], s[j][3]));
            }
            mx0 = fmaxf(mx0, __shfl_xor_sync(0xffffffff, mx0, 1));
            mx0 = fmaxf(mx0, __shfl_xor_sync(0xffffffff, mx0, 2));
            mx1 = fmaxf(mx1, __shfl_xor_sync(0xffffffff, mx1, 1));
            mx1 = fmaxf(mx1, __shfl_xor_sync(0xffffffff, mx1, 2));

            const float mn0 = fmaxf(m0, mx0);
            const float mn1 = fmaxf(m1, mx1);
            const float c0 = ex2f(m0 - mn0);
            const float c1 = ex2f(m1 - mn1);
            m0 = mn0; m1 = mn1;

#pragma unroll
            for (int j = 0; j < 8; j++) {
                o[j][0] *= c0; o[j][1] *= c0;
                o[j][2] *= c1; o[j][3] *= c1;
            }
            ol[0] *= c0; ol[1] *= c0; ol[2] *= c1; ol[3] *= c1;

#pragma unroll
            for (int t = 0; t < 4; t++) {
                const int j = 2 * t;
                ph[t][0] = h2ex2(pack_h2(s[j][0]   - mn0, s[j][1]   - mn0));
                ph[t][1] = h2ex2(pack_h2(s[j][2]   - mn1, s[j][3]   - mn1));
                ph[t][2] = h2ex2(pack_h2(s[j+1][0] - mn0, s[j+1][1] - mn0));
                ph[t][3] = h2ex2(pack_h2(s[j+1][2] - mn1, s[j+1][3] - mn1));
            }
        }

        // ---- O += P Vh ; l accumulates via ones column (col 64)
#pragma unroll
        for (int t = 0; t < 4; t++) {
#pragma unroll
            for (int jp = 0; jp < 2; jp++) {
                uint32_t vh[2][4];
#pragma unroll
                for (int i = 0; i < 2; i++) {
                    const int j2 = jp * 2 + i;
                    uint32_t off = ((t * 16 + (lid & 15)) * SK
                                    + j2 * 16 + (lid >> 4) * 8) * 2;
                    ldsm_x4_t(vh[i], uVh + off);
                }
#pragma unroll
                for (int i = 0; i < 2; i++) {
                    const int j2 = jp * 2 + i;
                    mma16816(o[j2 * 2],     ph[t], &vh[i][0]);
                    mma16816(o[j2 * 2 + 1], ph[t], &vh[i][2]);
                }
            }
            // ones column: n8 tile at col 64
            uint32_t ve[2];
            uint32_t off = ((t * 16 + (lid & 15)) * SK + 64) * 2;
            ldsm_x2_t(ve, uVh + off);
            mma16816(ol, ph[t], ve);
        }
    }

    // ---- epilogue: recover l from ones column, write fp16 attention output
    {
        const float l0 = __shfl_sync(0xffffffff, ol[0], lid & 28);
        const float l1 = __shfl_sync(0xffffffff, ol[2], lid & 28);
        const float inv0 = 1.f / l0;
        const float inv1 = 1.f / l1;
        const int gr0 = q0 + wid * 16 + (lid >> 2);
        const int col = h * HD + (lid & 3) * 2;
#pragma unroll
        for (int j = 0; j < 8; j++) {
            size_t i0 = (size_t)(b * SEQ + gr0) * DM + col + j * 8;
            size_t i1 = (size_t)(b * SEQ + gr0 + 8) * DM + col + j * 8;
            *(uint32_t*)(g_atth + i0) = pack_h2(o[j][0] * inv0, o[j][1] * inv0);
            *(uint32_t*)(g_atth + i1) = pack_h2(o[j][2] * inv1, o[j][3] * inv1);
        }
    }
}

// ---------------------------------------------------------------------------
extern "C" void kernel_launch(void* const* d_in, const int* in_sizes, int n_in,
                              void* d_out, int out_size)
{
    const float* x     = (const float*)d_in[0];   // [4,2048,1024]
    const float* w_qkv = (const float*)d_in[1];   // [1024,3072]
    const float* w_out = (const float*)d_in[2];   // [1024,1024]
    float* out = (float*)d_out;                   // [4,2048,1024]

    __half *xh, *wqh, *woh, *qkvh, *atth;
    cudaGetSymbolAddress((void**)&xh,   g_xh);
    cudaGetSymbolAddress((void**)&wqh,  g_wqh);
    cudaGetSymbolAddress((void**)&woh,  g_woh);
    cudaGetSymbolAddress((void**)&qkvh, g_qkvh);
    cudaGetSymbolAddress((void**)&atth, g_atth);

    cudaFuncSetAttribute(gemm_async,
                         cudaFuncAttributeMaxDynamicSharedMemorySize,
                         GEMM_SMEM_BYTES);
    cudaFuncSetAttribute(attn_hmma,
                         cudaFuncAttributeMaxDynamicSharedMemorySize,
                         ATTN_SMEM_BYTES);

    const float QSCALE = 0.125f * 1.4426950408889634f;   // (1/sqrt(64))*log2(e)

    // 0) convert inputs to fp16
    {
        int n4x = MROWS * DM / 4;
        cvt_kernel<<<(n4x + 255) / 256, 256>>>(x, xh, n4x);
        int n4q = DM * QKVN / 4;
        cvt_kernel<<<(n4q + 255) / 256, 256>>>(w_qkv, wqh, n4q);
        int n4o = DM * DM / 4;
        cvt_kernel<<<(n4o + 255) / 256, 256>>>(w_out, woh, n4o);
    }

    // 1) QKV projection -> fp16 (Q columns pre-scaled by QSCALE)
    {
        dim3 grid(QKVN / 256, MROWS / 128);
        gemm_async<<<grid, 512, GEMM_SMEM_BYTES>>>(
            xh, wqh, nullptr, qkvh, MROWS, QKVN, DM, QSCALE, DM);
    }

    // 2) Attention (HMMA flash, cp.async K/V)
    {
        dim3 grid(SEQ / 256, NH, BATCH);
        attn_hmma<<<grid, 512, ATTN_SMEM_BYTES>>>();
    }

    // 3) Output projection -> fp32 d_out
    {
        dim3 grid(DM / 256, MROWS / 128);
        gemm_async<<<grid, 512, GEMM_SMEM_BYTES>>>(
            atth, woh, out, nullptr, MROWS, DM, DM, 1.f, 0);
    }
}

// round 13
// speedup vs baseline: 1.0974x; 1.0974x over previous
#include <cuda_runtime.h>
#include <cuda_fp16.h>
#include <math.h>
#include <cstdint>

#define BATCH 4
#define SEQ   2048
#define DM    1024
#define NH    16
#define HD    64
#define QKVN  (3*DM)
#define MROWS (BATCH*SEQ)   // 8192

// ---------------------------------------------------------------------------
// Persistent fp16 arrays (no dynamic allocation allowed)
// ---------------------------------------------------------------------------
__device__ __half g_xh[(size_t)MROWS * DM];
__device__ __half g_wqh[(size_t)DM * QKVN];
__device__ __half g_woh[(size_t)DM * DM];
__device__ __half g_qkvh[(size_t)MROWS * QKVN];
__device__ __half g_atth[(size_t)MROWS * DM];

// ===========================================================================
// Helpers
// ===========================================================================
__device__ __forceinline__ void ldsm_x4(uint32_t* r, uint32_t addr) {
    asm volatile("ldmatrix.sync.aligned.m8n8.x4.shared.b16 {%0,%1,%2,%3}, [%4];"
        : "=r"(r[0]), "=r"(r[1]), "=r"(r[2]), "=r"(r[3]) : "r"(addr));
}
__device__ __forceinline__ void ldsm_x4_t(uint32_t* r, uint32_t addr) {
    asm volatile("ldmatrix.sync.aligned.m8n8.x4.trans.shared.b16 {%0,%1,%2,%3}, [%4];"
        : "=r"(r[0]), "=r"(r[1]), "=r"(r[2]), "=r"(r[3]) : "r"(addr));
}
__device__ __forceinline__ void ldsm_x2_t(uint32_t* r, uint32_t addr) {
    asm volatile("ldmatrix.sync.aligned.m8n8.x2.trans.shared.b16 {%0,%1}, [%2];"
        : "=r"(r[0]), "=r"(r[1]) : "r"(addr));
}
__device__ __forceinline__ void mma16816(float* d, const uint32_t* a, const uint32_t* b) {
    asm volatile(
        "mma.sync.aligned.m16n8k16.row.col.f32.f16.f16.f32 "
        "{%0,%1,%2,%3}, {%4,%5,%6,%7}, {%8,%9}, {%0,%1,%2,%3};"
        : "+f"(d[0]), "+f"(d[1]), "+f"(d[2]), "+f"(d[3])
        : "r"(a[0]), "r"(a[1]), "r"(a[2]), "r"(a[3]), "r"(b[0]), "r"(b[1]));
}
__device__ __forceinline__ uint32_t smem_to_u32(const void* smem_ptr) {
    uint32_t addr;
    asm("{ .reg .u64 tmp; cvta.to.shared.u64 tmp, %1; cvt.u32.u64 %0, tmp; }"
        : "=r"(addr) : "l"(smem_ptr));
    return addr;
}
__device__ __forceinline__ float ex2f(float x) {
    float y;
    asm("ex2.approx.f32 %0, %1;" : "=f"(y) : "f"(x));
    return y;
}
__device__ __forceinline__ uint32_t pack_h2(float x0, float x1) {
    __half2 t = __floats2half2_rn(x0, x1);
    return *(uint32_t*)&t;
}
__device__ __forceinline__ uint32_t h2ex2(uint32_t x) {
    uint32_t y;
    asm("ex2.approx.f16x2 %0, %1;" : "=r"(y) : "r"(x));
    return y;
}

#define CP_ASYNC16(saddr, gptr) \
    asm volatile("cp.async.cg.shared.global [%0], [%1], 16;" \
                 :: "r"(saddr), "l"(gptr))
#define CP_COMMIT()  asm volatile("cp.async.commit_group;")
#define CP_WAIT0()   asm volatile("cp.async.wait_group 0;")
#define CP_WAIT1()   asm volatile("cp.async.wait_group 1;")

// ===========================================================================
// Convert kernel: fp32 -> fp16 for all three inputs in one launch
// ===========================================================================
#define N4X (MROWS * DM / 4)
#define N4Q (DM * QKVN / 4)
#define N4O (DM * DM / 4)
__global__ void cvt_all(const float* __restrict__ x, const float* __restrict__ wq,
                        const float* __restrict__ wo)
{
    int i = blockIdx.x * blockDim.x + threadIdx.x;
    const float* s;
    __half* d;
    if (i < N4X)                  { s = x;  d = g_xh;  }
    else if (i < N4X + N4Q)       { s = wq; d = g_wqh; i -= N4X; }
    else if (i < N4X + N4Q + N4O) { s = wo; d = g_woh; i -= N4X + N4Q; }
    else return;
    float4 v = ((const float4*)s)[i];
    ((uint2*)d)[i] = make_uint2(pack_h2(v.x, v.y), pack_h2(v.z, v.w));
}

// ===========================================================================
// cp.async fp16 GEMM: C = A @ B, fp16 operands, fp32 accumulate.
// CTA tile 128x128, BK=32, 256 threads (8 warps, 32x64 warp tiles, 4x2).
// 3-stage cp.async ring; 2 CTAs/SM for cross-CTA latency hiding.
// ===========================================================================
#define GOA 0
#define GOB 10240                        // A: 128 rows x 80 B
#define GSTAGE_B 18944                   // + B: 32 rows x 272 B
#define GEMM_SMEM_BYTES (3 * GSTAGE_B)   // 56832

__global__ __launch_bounds__(256, 2)
void gemm_async(const __half* __restrict__ A, const __half* __restrict__ B,
                float* __restrict__ Cf, __half* __restrict__ Ch,
                int M, int N, int K, float qscale, int qcols)
{
    extern __shared__ char smem[];
    const uint32_t su = smem_to_u32(smem);

    const int tid = threadIdx.x;
    const int wid = tid >> 5;
    const int lid = tid & 31;
    const int brow = blockIdx.y * 128;
    const int bcol = blockIdx.x * 128;

    const int wr = wid >> 1;     // 0..3 -> m offset wr*32
    const int wc = wid & 1;      // 0..1 -> n offset wc*64

    const int nkt = K >> 5;

    // copy-thread assignments (256 threads)
    const int ar  = tid >> 1;            // A row 0..127
    const int ac2 = (tid & 1) * 2;       // A chunk base (2 chunks of 16B)
    const int br  = tid >> 3;            // B row 0..31
    const int bc2 = (tid & 7) * 2;       // B chunk base (2 chunks of 16B)

    auto issue_tile = [&](int kt) {
        const uint32_t sb = su + (uint32_t)(kt % 3) * GSTAGE_B;
        const int k0 = kt << 5;
        const __half* ga = A + (size_t)(brow + ar) * K + k0 + ac2 * 8;
        uint32_t sa = sb + GOA + ar * 80 + ac2 * 16;
        CP_ASYNC16(sa,      ga);
        CP_ASYNC16(sa + 16, ga + 8);
        const __half* gb = B + (size_t)(k0 + br) * N + bcol + bc2 * 8;
        uint32_t sbb = sb + GOB + br * 272 + bc2 * 16;
        CP_ASYNC16(sbb,      gb);
        CP_ASYNC16(sbb + 16, gb + 8);
    };

    float acc[2][8][4];
#pragma unroll
    for (int i = 0; i < 2; i++)
#pragma unroll
        for (int j = 0; j < 8; j++)
#pragma unroll
            for (int q = 0; q < 4; q++) acc[i][j][q] = 0.f;

    issue_tile(0); CP_COMMIT();
    issue_tile(1); CP_COMMIT();

    for (int kt = 0; kt < nkt; kt++) {
        if (kt + 1 < nkt) { CP_WAIT1(); } else { CP_WAIT0(); }
        __syncthreads();
        if (kt + 2 < nkt) { issue_tile(kt + 2); CP_COMMIT(); }

        const uint32_t sb = su + (uint32_t)(kt % 3) * GSTAGE_B;
#pragma unroll
        for (int ks = 0; ks < 2; ks++) {
            uint32_t ah[2][4];
#pragma unroll
            for (int mi = 0; mi < 2; mi++) {
                uint32_t row = wr * 32 + mi * 16 + (lid & 15);
                uint32_t col = ks * 16 + (lid >> 4) * 8;
                ldsm_x4(ah[mi], sb + GOA + row * 80 + col * 2);
            }
#pragma unroll
            for (int nbp = 0; nbp < 2; nbp++) {
                uint32_t bh[2][4];
#pragma unroll
                for (int i = 0; i < 2; i++) {
                    const int nb = nbp * 2 + i;
                    uint32_t row = ks * 16 + (lid & 15);
                    uint32_t col = wc * 64 + nb * 16 + (lid >> 4) * 8;
                    ldsm_x4_t(bh[i], sb + GOB + row * 272 + col * 2);
                }
#pragma unroll
                for (int i = 0; i < 2; i++) {
                    const int nb = nbp * 2 + i;
#pragma unroll
                    for (int mi = 0; mi < 2; mi++) {
                        mma16816(acc[mi][nb * 2],     ah[mi], &bh[i][0]);
                        mma16816(acc[mi][nb * 2 + 1], ah[mi], &bh[i][2]);
                    }
                }
            }
        }
    }

    // ---- epilogue ----
    const int qrow = lid >> 2;
    const int qcol = (lid & 3) * 2;
#pragma unroll
    for (int mi = 0; mi < 2; mi++) {
        int r0 = brow + wr * 32 + mi * 16 + qrow;
#pragma unroll
        for (int nb8 = 0; nb8 < 8; nb8++) {
            int c0 = bcol + wc * 64 + nb8 * 8 + qcol;
            float* d = acc[mi][nb8];
            if (Cf) {
                *(float2*)(Cf + (size_t)r0 * N + c0)       = make_float2(d[0], d[1]);
                *(float2*)(Cf + (size_t)(r0 + 8) * N + c0) = make_float2(d[2], d[3]);
            } else {
                const float sc = (c0 < qcols) ? qscale : 1.f;
                *(uint32_t*)(Ch + (size_t)r0 * N + c0)       = pack_h2(d[0] * sc, d[1] * sc);
                *(uint32_t*)(Ch + (size_t)(r0 + 8) * N + c0) = pack_h2(d[2] * sc, d[3] * sc);
            }
        }
    }
}

// ===========================================================================
// HMMA flash attention, pure fp16 operands, fp32 accumulate.
// Grid: (SEQ/128, NH, BATCH) = 1024 CTAs. 256 threads = 8 warps; warp w owns
// q rows [w*16, w*16+16). Q persists in smem; K/V 3-stage cp.async ring.
// 2 CTAs/SM: one CTA's softmax overlaps the other's MMAs.
// Row-sum l via ones-column in V; P exp via ex2.approx.f16x2.
// ===========================================================================
#define SK 72                          // fp16 elems per row (144 B stride)
#define AQ  0
#define AKV (128 * SK * 2)             // 18432
#define KVST (2 * 64 * SK * 2)         // 18432 per stage (K + V)
#define OKH  0
#define OVH  (64 * SK * 2)             // 9216
#define ATTN_SMEM_BYTES (AKV + 3 * KVST)   // 73728

__global__ __launch_bounds__(256, 2)
void attn_hmma()
{
    extern __shared__ char dsm[];
    const uint32_t su = smem_to_u32(dsm);

    const int tid = threadIdx.x;
    const int wid = tid >> 5;
    const int lid = tid & 31;
    const int b  = blockIdx.z;
    const int h  = blockIdx.y;
    const int q0 = blockIdx.x * 128;

    const uint32_t uQ = su + AQ;

    // KV copy (256 thr): arr = tid>>7 (0:K 1:V), row = (tid>>1)&63,
    // 64B half = (tid&1)
    const int cv_arr = tid >> 7;
    const int cv_r   = (tid >> 1) & 63;
    const int cv_c4  = (tid & 1) * 4;    // 16B-chunk base (4 chunks each)
    const int cv_col = DM + cv_arr * DM + h * HD + cv_c4 * 8;

    auto issue_kv = [&](int kb) {
        const uint32_t sb = su + AKV + (uint32_t)(kb % 3) * KVST
                            + cv_arr * (64 * SK * 2) + cv_r * (SK * 2) + cv_c4 * 16;
        const __half* gp = g_qkvh + (size_t)(b * SEQ + kb * 64 + cv_r) * QKVN + cv_col;
#pragma unroll
        for (int c = 0; c < 4; c++)
            CP_ASYNC16(sb + c * 16, gp + c * 8);
    };

    // ---- init ones-column (cols 64..71) in all 3 V stages
    for (int i = tid; i < 3 * 64; i += 256) {
        int st = i >> 6, r = i & 63;
        char* p = dsm + AKV + st * KVST + OVH + r * (SK * 2) + 128;
        *(uint4*)p = make_uint4(0x00003C00u, 0u, 0u, 0u);   // {1.0h, 0 x7}
    }

    // ---- issue Q + KV block 0 as group 0
    {
        const int qr = tid >> 1;            // 0..127
        const int qc = (tid & 1) * 32;
        const __half* gq = g_qkvh + (size_t)(b * SEQ + q0 + qr) * QKVN + h * HD + qc;
        uint32_t sq = uQ + qr * (SK * 2) + qc * 2;
#pragma unroll
        for (int c = 0; c < 4; c++)
            CP_ASYNC16(sq + c * 16, gq + c * 8);
    }
    issue_kv(0); CP_COMMIT();
    issue_kv(1); CP_COMMIT();

    float o[8][4];
#pragma unroll
    for (int j = 0; j < 8; j++)
#pragma unroll
        for (int q = 0; q < 4; q++) o[j][q] = 0.f;
    float ol[4] = {0.f, 0.f, 0.f, 0.f};     // ones-column accumulator (l)
    float m0 = -1e30f, m1 = -1e30f;

    for (int kb = 0; kb < SEQ / 64; kb++) {
        if (kb + 1 < SEQ / 64) { CP_WAIT1(); } else { CP_WAIT0(); }
        __syncthreads();
        if (kb + 2 < SEQ / 64) { issue_kv(kb + 2); CP_COMMIT(); }

        const uint32_t stB = su + AKV + (uint32_t)(kb % 3) * KVST;
        const uint32_t uKh = stB + OKH, uVh = stB + OVH;

        // ---- S = Q Kh^T  (16 x 64 per warp)
        float s[8][4];
#pragma unroll
        for (int j = 0; j < 8; j++)
#pragma unroll
            for (int q = 0; q < 4; q++) s[j][q] = 0.f;

#pragma unroll
        for (int t = 0; t < 4; t++) {
            uint32_t qh[4];
            {
                uint32_t row = wid * 16 + (lid & 15);
                uint32_t off = (row * SK + t * 16 + (lid >> 4) * 8) * 2;
                ldsm_x4(qh, uQ + off);
            }
#pragma unroll
            for (int jp = 0; jp < 2; jp++) {
                uint32_t kh[2][4];
#pragma unroll
                for (int i = 0; i < 2; i++) {
                    const int j2 = jp * 2 + i;
                    uint32_t off = ((j2 * 16 + (lid & 7) + ((lid >> 4) & 1) * 8) * SK
                                    + t * 16 + ((lid >> 3) & 1) * 8) * 2;
                    ldsm_x4(kh[i], uKh + off);
                }
#pragma unroll
                for (int i = 0; i < 2; i++) {
                    const int j2 = jp * 2 + i;
                    mma16816(s[j2 * 2],     qh, &kh[i][0]);
                    mma16816(s[j2 * 2 + 1], qh, &kh[i][2]);
                }
            }
        }

        // ---- online softmax (log2 domain): max, rescale, P = ex2.f16x2
        uint32_t ph[4][4];
        {
            float mx0 = s[0][0], mx1 = s[0][2];
#pragma unroll
            for (int j = 0; j < 8; j++) {
                mx0 = fmaxf(mx0, fmaxf(s[j][0], s[j][1]));
                mx1 = fmaxf(mx1, fmaxf(s[j][2], s[j][3]));
            }
            mx0 = fmaxf(mx0, __shfl_xor_sync(0xffffffff, mx0, 1));
            mx0 = fmaxf(mx0, __shfl_xor_sync(0xffffffff, mx0, 2));
            mx1 = fmaxf(mx1, __shfl_xor_sync(0xffffffff, mx1, 1));
            mx1 = fmaxf(mx1, __shfl_xor_sync(0xffffffff, mx1, 2));

            const float mn0 = fmaxf(m0, mx0);
            const float mn1 = fmaxf(m1, mx1);
            const float c0 = ex2f(m0 - mn0);
            const float c1 = ex2f(m1 - mn1);
            m0 = mn0; m1 = mn1;

#pragma unroll
            for (int j = 0; j < 8; j++) {
                o[j][0] *= c0; o[j][1] *= c0;
                o[j][2] *= c1; o[j][3] *= c1;
            }
            ol[0] *= c0; ol[1] *= c0; ol[2] *= c1; ol[3] *= c1;

#pragma unroll
            for (int t = 0; t < 4; t++) {
                const int j = 2 * t;
                ph[t][0] = h2ex2(pack_h2(s[j][0]   - mn0, s[j][1]   - mn0));
                ph[t][1] = h2ex2(pack_h2(s[j][2]   - mn1, s[j][3]   - mn1));
                ph[t][2] = h2ex2(pack_h2(s[j+1][0] - mn0, s[j+1][1] - mn0));
                ph[t][3] = h2ex2(pack_h2(s[j+1][2] - mn1, s[j+1][3] - mn1));
            }
        }

        // ---- O += P Vh ; l accumulates via ones column (col 64)
#pragma unroll
        for (int t = 0; t < 4; t++) {
#pragma unroll
            for (int jp = 0; jp < 2; jp++) {
                uint32_t vh[2][4];
#pragma unroll
                for (int i = 0; i < 2; i++) {
                    const int j2 = jp * 2 + i;
                    uint32_t off = ((t * 16 + (lid & 15)) * SK
                                    + j2 * 16 + (lid >> 4) * 8) * 2;
                    ldsm_x4_t(vh[i], uVh + off);
                }
#pragma unroll
                for (int i = 0; i < 2; i++) {
                    const int j2 = jp * 2 + i;
                    mma16816(o[j2 * 2],     ph[t], &vh[i][0]);
                    mma16816(o[j2 * 2 + 1], ph[t], &vh[i][2]);
                }
            }
            // ones column: n8 tile at col 64
            uint32_t ve[2];
            uint32_t off = ((t * 16 + (lid & 15)) * SK + 64) * 2;
            ldsm_x2_t(ve, uVh + off);
            mma16816(ol, ph[t], ve);
        }
    }

    // ---- epilogue: recover l from ones column, write fp16 attention output
    {
        const float l0 = __shfl_sync(0xffffffff, ol[0], lid & 28);
        const float l1 = __shfl_sync(0xffffffff, ol[2], lid & 28);
        const float inv0 = 1.f / l0;
        const float inv1 = 1.f / l1;
        const int gr0 = q0 + wid * 16 + (lid >> 2);
        const int col = h * HD + (lid & 3) * 2;
#pragma unroll
        for (int j = 0; j < 8; j++) {
            size_t i0 = (size_t)(b * SEQ + gr0) * DM + col + j * 8;
            size_t i1 = (size_t)(b * SEQ + gr0 + 8) * DM + col + j * 8;
            *(uint32_t*)(g_atth + i0) = pack_h2(o[j][0] * inv0, o[j][1] * inv0);
            *(uint32_t*)(g_atth + i1) = pack_h2(o[j][2] * inv1, o[j][3] * inv1);
        }
    }
}

// ---------------------------------------------------------------------------
extern "C" void kernel_launch(void* const* d_in, const int* in_sizes, int n_in,
                              void* d_out, int out_size)
{
    const float* x     = (const float*)d_in[0];   // [4,2048,1024]
    const float* w_qkv = (const float*)d_in[1];   // [1024,3072]
    const float* w_out = (const float*)d_in[2];   // [1024,1024]
    float* out = (float*)d_out;                   // [4,2048,1024]

    __half *xh, *wqh, *woh, *qkvh, *atth;
    cudaGetSymbolAddress((void**)&xh,   g_xh);
    cudaGetSymbolAddress((void**)&wqh,  g_wqh);
    cudaGetSymbolAddress((void**)&woh,  g_woh);
    cudaGetSymbolAddress((void**)&qkvh, g_qkvh);
    cudaGetSymbolAddress((void**)&atth, g_atth);

    cudaFuncSetAttribute(gemm_async,
                         cudaFuncAttributeMaxDynamicSharedMemorySize,
                         GEMM_SMEM_BYTES);
    cudaFuncSetAttribute(attn_hmma,
                         cudaFuncAttributeMaxDynamicSharedMemorySize,
                         ATTN_SMEM_BYTES);

    const float QSCALE = 0.125f * 1.4426950408889634f;   // (1/sqrt(64))*log2(e)

    // 0) convert inputs to fp16 (single launch)
    {
        int n4 = N4X + N4Q + N4O;
        cvt_all<<<(n4 + 255) / 256, 256>>>(x, w_qkv, w_out);
    }

    // 1) QKV projection -> fp16 (Q columns pre-scaled by QSCALE)
    {
        dim3 grid(QKVN / 128, MROWS / 128);
        gemm_async<<<grid, 256, GEMM_SMEM_BYTES>>>(
            xh, wqh, nullptr, qkvh, MROWS, QKVN, DM, QSCALE, DM);
    }

    // 2) Attention (HMMA flash, cp.async K/V)
    {
        dim3 grid(SEQ / 128, NH, BATCH);
        attn_hmma<<<grid, 256, ATTN_SMEM_BYTES>>>();
    }

    // 3) Output projection -> fp32 d_out
    {
        dim3 grid(DM / 128, MROWS / 128);
        gemm_async<<<grid, 256, GEMM_SMEM_BYTES>>>(
            atth, woh, out, nullptr, MROWS, DM, DM, 1.f, 0);
    }
}